// round 1
// baseline (speedup 1.0000x reference)
#include <cuda_runtime.h>
#include <math.h>

#define BATCH   16
#define SEQ     512
#define DIMC    2048
#define NH      16
#define HD      128
#define TOKENS  (BATCH*SEQ)          /* 8192 */
#define QKVCOLS (3*DIMC)             /* 6144 */

// Scratch (allocation-free rule: __device__ globals)
__device__ float g_qkv[(size_t)TOKENS * QKVCOLS];   // [token][3*2048]
__device__ float g_y  [(size_t)TOKENS * DIMC];      // [token][2048]

// ---------------------------------------------------------------------------
// fp32 GEMM: C[M,N] = A[M,K] @ B[K,N], all row-major. 128x128x16 tile,
// 256 threads, 8x8 per-thread register tile, float4 smem fragments.
// ---------------------------------------------------------------------------
__global__ __launch_bounds__(256) void gemm128(const float* __restrict__ A,
                                               const float* __restrict__ B,
                                               float*       __restrict__ C,
                                               int M, int N, int K)
{
    __shared__ float As[16][132];   // transposed A tile: As[k][row]
    __shared__ float Bs[16][128];   // Bs[k][col]

    const int tid = threadIdx.x;
    const int tx  = tid & 15;       // 0..15 -> col group
    const int ty  = tid >> 4;       // 0..15 -> row group
    const int row0 = blockIdx.y * 128;
    const int col0 = blockIdx.x * 128;

    float acc[8][8];
#pragma unroll
    for (int i = 0; i < 8; i++)
#pragma unroll
        for (int j = 0; j < 8; j++) acc[i][j] = 0.f;

    const int ar = tid >> 2;           // 0..63
    const int ac = (tid & 3) << 2;     // 0,4,8,12
    const int br = tid >> 5;           // 0..7
    const int bc = (tid & 31) << 2;    // 0..124

    for (int k0 = 0; k0 < K; k0 += 16) {
#pragma unroll
        for (int rr = 0; rr < 128; rr += 64) {
            float4 v = *(const float4*)(A + (size_t)(row0 + ar + rr) * K + (k0 + ac));
            As[ac + 0][ar + rr] = v.x;
            As[ac + 1][ar + rr] = v.y;
            As[ac + 2][ar + rr] = v.z;
            As[ac + 3][ar + rr] = v.w;
        }
#pragma unroll
        for (int rr = 0; rr < 16; rr += 8) {
            *(float4*)&Bs[br + rr][bc] =
                *(const float4*)(B + (size_t)(k0 + br + rr) * N + (col0 + bc));
        }
        __syncthreads();

#pragma unroll
        for (int kk = 0; kk < 16; kk++) {
            float a[8], b[8];
            *(float4*)&a[0] = *(float4*)&As[kk][ty * 8];
            *(float4*)&a[4] = *(float4*)&As[kk][ty * 8 + 4];
            *(float4*)&b[0] = *(float4*)&Bs[kk][tx * 8];
            *(float4*)&b[4] = *(float4*)&Bs[kk][tx * 8 + 4];
#pragma unroll
            for (int i = 0; i < 8; i++)
#pragma unroll
                for (int j = 0; j < 8; j++)
                    acc[i][j] = fmaf(a[i], b[j], acc[i][j]);
        }
        __syncthreads();
    }

#pragma unroll
    for (int i = 0; i < 8; i++) {
        float* crow = C + (size_t)(row0 + ty * 8 + i) * N + col0 + tx * 8;
        *(float4*)(crow)     = make_float4(acc[i][0], acc[i][1], acc[i][2], acc[i][3]);
        *(float4*)(crow + 4) = make_float4(acc[i][4], acc[i][5], acc[i][6], acc[i][7]);
    }
}

// ---------------------------------------------------------------------------
// RoPE in-place on g_qkv (q at col 0, k at col DIMC). First 16 dims/head:
// out[i]   = x[i]*cos - x[i+8]*sin
// out[i+8] = x[i+8]*cos + x[i]*sin,  freq_i = t * 10000^(-i/8), i=0..7
// cos/sin of the fp32-rounded freq computed in double -> matches jnp fp32.
// ---------------------------------------------------------------------------
__global__ void rope_kernel()
{
    int idx = blockIdx.x * blockDim.x + threadIdx.x;   // 16*512*2*16 total
    int h = idx & 15;
    int s = (idx >> 4) & 1;          // 0 = q, 1 = k
    int t = (idx >> 5) & 511;
    int b = idx >> 14;
    size_t base = ((size_t)(b * SEQ + t)) * QKVCOLS + (size_t)s * DIMC + h * HD;
#pragma unroll
    for (int i = 0; i < 8; i++) {
        float inv  = (float)pow(10000.0, -(double)i / 8.0);
        float freq = (float)t * inv;
        float c  = (float)cos((double)freq);
        float sn = (float)sin((double)freq);
        float x1 = g_qkv[base + i];
        float x2 = g_qkv[base + 8 + i];
        g_qkv[base + i]     = x1 * c - x2 * sn;
        g_qkv[base + 8 + i] = x2 * c + x1 * sn;
    }
}

// ---------------------------------------------------------------------------
// Flash-style fp32 causal attention. One CTA = (64 q-rows, one (b,h)).
// Q,K stored d-major (transposed) in smem for conflict-free float4 frags.
// ---------------------------------------------------------------------------
#define QT_S 68     // padded stride for Qt/Kt ([128][68])
#define V_S  132    // padded stride for Vs  ([64][132])
#define S_S  68     // padded stride for Ss  ([64][68])
#define ATTN_SMEM_FLOATS (128*QT_S*2 + 64*V_S + 64*S_S + 192)

__global__ __launch_bounds__(256) void attn_kernel()
{
    extern __shared__ float sm[];
    float* Qt = sm;                       // [128][68] Qt[d][r]
    float* Kt = Qt + 128 * QT_S;          // [128][68] Kt[d][c]
    float* Vs = Kt + 128 * QT_S;          // [64][132] Vs[r][d]
    float* Ss = Vs + 64  * V_S;           // [64][68]
    float* mS = Ss + 64  * S_S;           // [64]
    float* lS = mS + 64;                  // [64]
    float* aS = lS + 64;                  // [64]

    const int tid = threadIdx.x;
    const int tx = tid & 15, ty = tid >> 4;
    const int qt = blockIdx.x;            // q tile 0..7
    const int h  = blockIdx.y;
    const int b  = blockIdx.z;
    const int q0 = qt * 64;
    const float scale = 0.08838834764831845f;   // 1/sqrt(128)

    // Load Q tile (scaled), transposed. float4 global loads, scalar smem scatter.
    for (int i4 = tid; i4 < 64 * 32; i4 += 256) {
        int r = i4 >> 5;
        int d = (i4 & 31) << 2;
        float4 v = *(const float4*)(g_qkv + ((size_t)(b * SEQ + q0 + r)) * QKVCOLS + h * HD + d);
        Qt[(d + 0) * QT_S + r] = v.x * scale;
        Qt[(d + 1) * QT_S + r] = v.y * scale;
        Qt[(d + 2) * QT_S + r] = v.z * scale;
        Qt[(d + 3) * QT_S + r] = v.w * scale;
    }
    if (tid < 64) { mS[tid] = -INFINITY; lS[tid] = 0.f; }

    float y[4][8];
#pragma unroll
    for (int i = 0; i < 4; i++)
#pragma unroll
        for (int j = 0; j < 8; j++) y[i][j] = 0.f;

    for (int kt = 0; kt <= qt; kt++) {
        const int k0 = kt * 64;
        __syncthreads();   // Q ready (iter 0) / prev-iter consumers done

        for (int i4 = tid; i4 < 64 * 32; i4 += 256) {
            int r = i4 >> 5;
            int d = (i4 & 31) << 2;
            size_t rowbase = ((size_t)(b * SEQ + k0 + r)) * QKVCOLS + h * HD + d;
            float4 kv = *(const float4*)(g_qkv + rowbase + DIMC);
            float4 vv = *(const float4*)(g_qkv + rowbase + 2 * DIMC);
            Kt[(d + 0) * QT_S + r] = kv.x;
            Kt[(d + 1) * QT_S + r] = kv.y;
            Kt[(d + 2) * QT_S + r] = kv.z;
            Kt[(d + 3) * QT_S + r] = kv.w;
            *(float4*)&Vs[r * V_S + d] = vv;
        }
        __syncthreads();

        // S = Q @ K^T (4x4 per thread: rows ty*4+i, cols tx*4+j)
        float s_acc[4][4];
#pragma unroll
        for (int i = 0; i < 4; i++)
#pragma unroll
            for (int j = 0; j < 4; j++) s_acc[i][j] = 0.f;

#pragma unroll 4
        for (int d = 0; d < 128; d++) {
            float4 qf = *(float4*)&Qt[d * QT_S + ty * 4];
            float4 kf = *(float4*)&Kt[d * QT_S + tx * 4];
            float qa[4] = {qf.x, qf.y, qf.z, qf.w};
            float ka[4] = {kf.x, kf.y, kf.z, kf.w};
#pragma unroll
            for (int i = 0; i < 4; i++)
#pragma unroll
                for (int j = 0; j < 4; j++)
                    s_acc[i][j] = fmaf(qa[i], ka[j], s_acc[i][j]);
        }
#pragma unroll
        for (int i = 0; i < 4; i++)
            *(float4*)&Ss[(ty * 4 + i) * S_S + tx * 4] =
                make_float4(s_acc[i][0], s_acc[i][1], s_acc[i][2], s_acc[i][3]);
        __syncthreads();

        // Online softmax (row-per-thread, 64 rows)
        if (tid < 64) {
            int r = tid;
            int cmax = (kt == qt) ? (r + 1) : 64;   // causal: cols [0, cmax)
            float mold = mS[r];
            float mx = mold;
            for (int c = 0; c < cmax; c++) mx = fmaxf(mx, Ss[r * S_S + c]);
            float alpha = expf(mold - mx);
            float sum = 0.f;
            for (int c = 0; c < 64; c++) {
                float p = (c < cmax) ? expf(Ss[r * S_S + c] - mx) : 0.f;
                Ss[r * S_S + c] = p;
                sum += p;
            }
            lS[r] = lS[r] * alpha + sum;
            mS[r] = mx;
            aS[r] = alpha;
        }
        __syncthreads();

        // Rescale and accumulate Y += P @ V (rows ty*4+i, cols tx*8+j)
#pragma unroll
        for (int i = 0; i < 4; i++) {
            float al = aS[ty * 4 + i];
#pragma unroll
            for (int j = 0; j < 8; j++) y[i][j] *= al;
        }
#pragma unroll 2
        for (int kk = 0; kk < 64; kk++) {
            float p[4];
#pragma unroll
            for (int i = 0; i < 4; i++) p[i] = Ss[(ty * 4 + i) * S_S + kk];
            float4 v0 = *(float4*)&Vs[kk * V_S + tx * 8];
            float4 v1 = *(float4*)&Vs[kk * V_S + tx * 8 + 4];
            float va[8] = {v0.x, v0.y, v0.z, v0.w, v1.x, v1.y, v1.z, v1.w};
#pragma unroll
            for (int i = 0; i < 4; i++)
#pragma unroll
                for (int j = 0; j < 8; j++)
                    y[i][j] = fmaf(p[i], va[j], y[i][j]);
        }
    }

    // Epilogue: y / l, write to g_y[b,t,h,d]
#pragma unroll
    for (int i = 0; i < 4; i++) {
        int r = ty * 4 + i;
        float invl = 1.f / lS[r];
        float* dst = g_y + ((size_t)(b * SEQ + q0 + r)) * DIMC + h * HD + tx * 8;
        *(float4*)(dst)     = make_float4(y[i][0] * invl, y[i][1] * invl,
                                          y[i][2] * invl, y[i][3] * invl);
        *(float4*)(dst + 4) = make_float4(y[i][4] * invl, y[i][5] * invl,
                                          y[i][6] * invl, y[i][7] * invl);
    }
}

// ---------------------------------------------------------------------------
extern "C" void kernel_launch(void* const* d_in, const int* in_sizes, int n_in,
                              void* d_out, int out_size)
{
    const float* x    = (const float*)d_in[0];
    const float* Wqkv = (const float*)d_in[1];
    const float* Wout = (const float*)d_in[2];
    float*       out  = (float*)d_out;

    float *qkv_ptr, *y_ptr;
    cudaGetSymbolAddress((void**)&qkv_ptr, g_qkv);
    cudaGetSymbolAddress((void**)&y_ptr,   g_y);

    // 1) QKV projection: [8192,2048] @ [2048,6144]
    gemm128<<<dim3(QKVCOLS / 128, TOKENS / 128), 256>>>(x, Wqkv, qkv_ptr,
                                                        TOKENS, QKVCOLS, DIMC);
    // 2) RoPE on q,k (first 16 dims/head)
    rope_kernel<<<(BATCH * SEQ * 2 * NH) / 256, 256>>>();

    // 3) Attention
    cudaFuncSetAttribute(attn_kernel, cudaFuncAttributeMaxDynamicSharedMemorySize,
                         ATTN_SMEM_FLOATS * sizeof(float));
    attn_kernel<<<dim3(SEQ / 64, NH, BATCH), 256, ATTN_SMEM_FLOATS * sizeof(float)>>>();

    // 4) Output projection: [8192,2048] @ [2048,2048]
    gemm128<<<dim3(DIMC / 128, TOKENS / 128), 256>>>(y_ptr, Wout, out,
                                                     TOKENS, DIMC, DIMC);
}

// round 8
// speedup vs baseline: 2.2080x; 2.2080x over previous
#include <cuda_runtime.h>
#include <math.h>
#include <stdint.h>

#define BATCH   16
#define SEQ     512
#define DIMC    2048
#define NH      16
#define HD      128
#define TOKENS  (BATCH*SEQ)          /* 8192 */
#define QKVCOLS (3*DIMC)             /* 6144 */
#define KDIM    2048

// ---------------- scratch (__device__ globals, allocation-free rule) --------
__device__ __align__(1024) float g_qkv   [(size_t)TOKENS * QKVCOLS];  // 201MB
__device__ __align__(1024) float g_y     [(size_t)TOKENS * DIMC];     // 67MB (octet-permuted, tf32)
__device__ __align__(1024) float g_xr    [(size_t)TOKENS * DIMC];     // 67MB (octet-permuted, tf32)
__device__ __align__(1024) float g_wqkv_t[(size_t)QKVCOLS * KDIM];    // 50MB [N][K] perm, tf32
__device__ __align__(1024) float g_wout_t[(size_t)DIMC    * KDIM];    // 16MB [N][K] perm, tf32

// ---------------- helpers ---------------------------------------------------
__device__ __forceinline__ uint32_t smem_u32(const void* p) {
    uint32_t a;
    asm("{ .reg .u64 t; cvta.to.shared.u64 t, %1; cvt.u32.u64 %0, t; }" : "=r"(a) : "l"(p));
    return a;
}
__device__ __forceinline__ float tf32r(float x) {
    uint32_t u;
    asm("cvt.rna.tf32.f32 %0, %1;" : "=r"(u) : "f"(x));
    return __uint_as_float(u);
}
#define CP_ASYNC16(dst, src) \
    asm volatile("cp.async.cg.shared.global [%0], [%1], 16;" :: "r"(dst), "l"(src))
#define CP_COMMIT()  asm volatile("cp.async.commit_group;" ::: "memory")
#define CP_WAIT(n)   asm volatile("cp.async.wait_group %0;" :: "n"(n) : "memory")

// m16n8k8 tf32 mma, fp32 accumulate (baseline PTX, works on compute_103)
__device__ __forceinline__ void mma16n8k8(float* d, const uint32_t* a, const uint32_t* b) {
    asm volatile("mma.sync.aligned.m16n8k8.row.col.f32.tf32.tf32.f32 "
                 "{%0,%1,%2,%3}, {%4,%5,%6,%7}, {%8,%9}, {%0,%1,%2,%3};"
                 : "+f"(d[0]), "+f"(d[1]), "+f"(d[2]), "+f"(d[3])
                 : "r"(a[0]), "r"(a[1]), "r"(a[2]), "r"(a[3]),
                   "r"(b[0]), "r"(b[1]));
}

// ---------------------------------------------------------------------------
// tf32 mma.sync GEMM: C[M,N] = A[M,K] @ Bt[N,K]^T, K=2048.
// A and Bt are octet-permuted along K: within each group of 8 consecutive k,
// physical order = [k0,k4,k1,k5,k2,k6,k3,k7], so that a thread's (q, q+4)
// fragment pair is one contiguous float2 in shared memory.
// BM=128, BN=256, BK=32, 256 threads, 8 warps (2m x 4n), warp tile 64x64.
// ---------------------------------------------------------------------------
#define GBM   128
#define GBN   256
#define GBK   32
#define GNST  3
#define A_ROWSTRIDE 40                 /* floats: 32 data + 8 pad */
#define A_ST  (GBM * A_ROWSTRIDE * 4)  /* 20480 B */
#define B_ST  (GBN * A_ROWSTRIDE * 4)  /* 40960 B */
#define GEMM_SMEM (GNST * (A_ST + B_ST))  /* 184320 B */
#define NCHUNK (KDIM / GBK)            /* 64 */

__device__ __forceinline__ void g_load_stage(const float* __restrict__ A,
                                             const float* __restrict__ Bt,
                                             uint32_t smem0, int s, int kc,
                                             int tid, int row0, int col0) {
    const int k0 = kc * GBK;
    const uint32_t a_base = smem0 + s * A_ST;
    const uint32_t b_base = smem0 + GNST * A_ST + s * B_ST;
#pragma unroll
    for (int i = 0; i < 4; i++) {              // A: 128 rows x 8 chunks
        int idx = tid + i * 256;
        int r = idx >> 3, seg = idx & 7;
        CP_ASYNC16(a_base + (uint32_t)(r * A_ROWSTRIDE + seg * 4) * 4,
                   A + (size_t)(row0 + r) * KDIM + k0 + seg * 4);
    }
#pragma unroll
    for (int i = 0; i < 8; i++) {              // B: 256 rows x 8 chunks
        int idx = tid + i * 256;
        int r = idx >> 3, seg = idx & 7;
        CP_ASYNC16(b_base + (uint32_t)(r * A_ROWSTRIDE + seg * 4) * 4,
                   Bt + (size_t)(col0 + r) * KDIM + k0 + seg * 4);
    }
    CP_COMMIT();
}

__global__ __launch_bounds__(256, 1) void gemm_mma(const float* __restrict__ A,
                                                   const float* __restrict__ Bt,
                                                   float*       __restrict__ C,
                                                   int N) {
    extern __shared__ char sm_raw[];
    const uint32_t smem0 = smem_u32(sm_raw);
    const int tid  = threadIdx.x;
    const int lane = tid & 31, wid = tid >> 5;
    const int wm = wid & 1, wn = wid >> 1;        // warp grid 2(m) x 4(n)
    const int q  = lane & 3, gr = lane >> 2;
    const int row0 = blockIdx.y * GBM;
    const int col0 = blockIdx.x * GBN;

    float acc[4][8][4];
#pragma unroll
    for (int mi = 0; mi < 4; mi++)
#pragma unroll
        for (int ni = 0; ni < 8; ni++)
#pragma unroll
            for (int v = 0; v < 4; v++) acc[mi][ni][v] = 0.f;

    g_load_stage(A, Bt, smem0, 0, 0, tid, row0, col0);
    g_load_stage(A, Bt, smem0, 1, 1, tid, row0, col0);

    for (int c = 0; c < NCHUNK; c++) {
        const int s = c % GNST;
        if (c + 2 < NCHUNK) {
            CP_WAIT(1);
            __syncthreads();
            g_load_stage(A, Bt, smem0, (c + 2) % GNST, c + 2, tid, row0, col0);
        } else {
            CP_WAIT(0);
            __syncthreads();
        }

        const float2* As = (const float2*)(sm_raw + s * A_ST);
        const float2* Bs = (const float2*)(sm_raw + GNST * A_ST + s * B_ST);
        // float2 row stride = 20; frag at col (kg*4 + q) float2s

#pragma unroll
        for (int kg = 0; kg < 4; kg++) {
            uint32_t af[4][4], bf[8][2];
#pragma unroll
            for (int mi = 0; mi < 4; mi++) {
                int rowm = wm * 64 + mi * 16 + gr;
                float2 lo = As[rowm * 20 + kg * 4 + q];
                float2 hi = As[(rowm + 8) * 20 + kg * 4 + q];
                af[mi][0] = __float_as_uint(lo.x);
                af[mi][1] = __float_as_uint(hi.x);
                af[mi][2] = __float_as_uint(lo.y);
                af[mi][3] = __float_as_uint(hi.y);
            }
#pragma unroll
            for (int ni = 0; ni < 8; ni++) {
                int rown = wn * 64 + ni * 8 + gr;
                float2 bv = Bs[rown * 20 + kg * 4 + q];
                bf[ni][0] = __float_as_uint(bv.x);
                bf[ni][1] = __float_as_uint(bv.y);
            }
#pragma unroll
            for (int mi = 0; mi < 4; mi++)
#pragma unroll
                for (int ni = 0; ni < 8; ni++)
                    mma16n8k8(acc[mi][ni], af[mi], bf[ni]);
        }
    }

    // epilogue: c0,c1 at (row, 2q..2q+1), c2,c3 at (row+8, same cols)
#pragma unroll
    for (int mi = 0; mi < 4; mi++) {
        int rowm = row0 + wm * 64 + mi * 16 + gr;
#pragma unroll
        for (int ni = 0; ni < 8; ni++) {
            int col = col0 + wn * 64 + ni * 8 + 2 * q;
            *(float2*)(C + (size_t)rowm * N + col) =
                make_float2(acc[mi][ni][0], acc[mi][ni][1]);
            *(float2*)(C + (size_t)(rowm + 8) * N + col) =
                make_float2(acc[mi][ni][2], acc[mi][ni][3]);
        }
    }
}

// ---------------------------------------------------------------------------
// prep: octet-permute + tf32-round x (elementwise along K)
// out[8g+2q] = in[8g+q], out[8g+2q+1] = in[8g+q+4]
// ---------------------------------------------------------------------------
__global__ void permute_cvt_x(const float* __restrict__ x) {
    size_t o = ((size_t)blockIdx.x * 256 + threadIdx.x) * 8;
    float4 v0 = *(const float4*)(x + o);
    float4 v1 = *(const float4*)(x + o + 4);
    float4 o0 = make_float4(tf32r(v0.x), tf32r(v1.x), tf32r(v0.y), tf32r(v1.y));
    float4 o1 = make_float4(tf32r(v0.z), tf32r(v1.z), tf32r(v0.w), tf32r(v1.w));
    *(float4*)(g_xr + o)     = o0;
    *(float4*)(g_xr + o + 4) = o1;
}

// transpose W [K][N] -> Wt [N][K], octet-permute along output K, tf32-round
__global__ void transpose_permute_cvt(const float* __restrict__ W,
                                      float* __restrict__ Wt, int N) {
    __shared__ float t[32][33];
    int k0 = blockIdx.y * 32, n0 = blockIdx.x * 32;
    int tx = threadIdx.x, ty = threadIdx.y;
#pragma unroll
    for (int i = 0; i < 32; i += 8)
        t[ty + i][tx] = W[(size_t)(k0 + ty + i) * N + n0 + tx];
    __syncthreads();
    // phys col tx -> logical k within tile
    int g = tx >> 3, p = tx & 7;
    int lk = g * 8 + (p >> 1) + ((p & 1) << 2);
#pragma unroll
    for (int i = 0; i < 32; i += 8)
        Wt[(size_t)(n0 + ty + i) * KDIM + k0 + tx] = tf32r(t[lk][ty + i]);
}

// ---------------------------------------------------------------------------
// RoPE (unchanged, validated)
// ---------------------------------------------------------------------------
__global__ void rope_kernel() {
    int idx = blockIdx.x * blockDim.x + threadIdx.x;
    int h = idx & 15;
    int s = (idx >> 4) & 1;
    int t = (idx >> 5) & 511;
    int b = idx >> 14;
    size_t base = ((size_t)(b * SEQ + t)) * QKVCOLS + (size_t)s * DIMC + h * HD;
#pragma unroll
    for (int i = 0; i < 8; i++) {
        float inv  = (float)pow(10000.0, -(double)i / 8.0);
        float freq = (float)t * inv;
        float c  = (float)cos((double)freq);
        float sn = (float)sin((double)freq);
        float x1 = g_qkv[base + i];
        float x2 = g_qkv[base + 8 + i];
        g_qkv[base + i]     = x1 * c - x2 * sn;
        g_qkv[base + 8 + i] = x2 * c + x1 * sn;
    }
}

// ---------------------------------------------------------------------------
// Flash-style fp32 causal attention (validated R1) — epilogue now writes
// octet-permuted + tf32-rounded y (feeds gemm_mma directly).
// ---------------------------------------------------------------------------
#define QT_S 68
#define V_S  132
#define S_S  68
#define ATTN_SMEM_FLOATS (128*QT_S*2 + 64*V_S + 64*S_S + 192)

__global__ __launch_bounds__(256) void attn_kernel() {
    extern __shared__ float sm[];
    float* Qt = sm;
    float* Kt = Qt + 128 * QT_S;
    float* Vs = Kt + 128 * QT_S;
    float* Ss = Vs + 64  * V_S;
    float* mS = Ss + 64  * S_S;
    float* lS = mS + 64;
    float* aS = lS + 64;

    const int tid = threadIdx.x;
    const int tx = tid & 15, ty = tid >> 4;
    const int qt = blockIdx.x;
    const int h  = blockIdx.y;
    const int b  = blockIdx.z;
    const int q0 = qt * 64;
    const float scale = 0.08838834764831845f;

    for (int i4 = tid; i4 < 64 * 32; i4 += 256) {
        int r = i4 >> 5;
        int d = (i4 & 31) << 2;
        float4 v = *(const float4*)(g_qkv + ((size_t)(b * SEQ + q0 + r)) * QKVCOLS + h * HD + d);
        Qt[(d + 0) * QT_S + r] = v.x * scale;
        Qt[(d + 1) * QT_S + r] = v.y * scale;
        Qt[(d + 2) * QT_S + r] = v.z * scale;
        Qt[(d + 3) * QT_S + r] = v.w * scale;
    }
    if (tid < 64) { mS[tid] = -INFINITY; lS[tid] = 0.f; }

    float y[4][8];
#pragma unroll
    for (int i = 0; i < 4; i++)
#pragma unroll
        for (int j = 0; j < 8; j++) y[i][j] = 0.f;

    for (int kt = 0; kt <= qt; kt++) {
        const int k0 = kt * 64;
        __syncthreads();

        for (int i4 = tid; i4 < 64 * 32; i4 += 256) {
            int r = i4 >> 5;
            int d = (i4 & 31) << 2;
            size_t rowbase = ((size_t)(b * SEQ + k0 + r)) * QKVCOLS + h * HD + d;
            float4 kv = *(const float4*)(g_qkv + rowbase + DIMC);
            float4 vv = *(const float4*)(g_qkv + rowbase + 2 * DIMC);
            Kt[(d + 0) * QT_S + r] = kv.x;
            Kt[(d + 1) * QT_S + r] = kv.y;
            Kt[(d + 2) * QT_S + r] = kv.z;
            Kt[(d + 3) * QT_S + r] = kv.w;
            *(float4*)&Vs[r * V_S + d] = vv;
        }
        __syncthreads();

        float s_acc[4][4];
#pragma unroll
        for (int i = 0; i < 4; i++)
#pragma unroll
            for (int j = 0; j < 4; j++) s_acc[i][j] = 0.f;

#pragma unroll 4
        for (int d = 0; d < 128; d++) {
            float4 qf = *(float4*)&Qt[d * QT_S + ty * 4];
            float4 kf = *(float4*)&Kt[d * QT_S + tx * 4];
            float qa[4] = {qf.x, qf.y, qf.z, qf.w};
            float ka[4] = {kf.x, kf.y, kf.z, kf.w};
#pragma unroll
            for (int i = 0; i < 4; i++)
#pragma unroll
                for (int j = 0; j < 4; j++)
                    s_acc[i][j] = fmaf(qa[i], ka[j], s_acc[i][j]);
        }
#pragma unroll
        for (int i = 0; i < 4; i++)
            *(float4*)&Ss[(ty * 4 + i) * S_S + tx * 4] =
                make_float4(s_acc[i][0], s_acc[i][1], s_acc[i][2], s_acc[i][3]);
        __syncthreads();

        if (tid < 64) {
            int r = tid;
            int cmax = (kt == qt) ? (r + 1) : 64;
            float mold = mS[r];
            float mx = mold;
            for (int c = 0; c < cmax; c++) mx = fmaxf(mx, Ss[r * S_S + c]);
            float alpha = expf(mold - mx);
            float sum = 0.f;
            for (int c = 0; c < 64; c++) {
                float p = (c < cmax) ? expf(Ss[r * S_S + c] - mx) : 0.f;
                Ss[r * S_S + c] = p;
                sum += p;
            }
            lS[r] = lS[r] * alpha + sum;
            mS[r] = mx;
            aS[r] = alpha;
        }
        __syncthreads();

#pragma unroll
        for (int i = 0; i < 4; i++) {
            float al = aS[ty * 4 + i];
#pragma unroll
            for (int j = 0; j < 8; j++) y[i][j] *= al;
        }
#pragma unroll 2
        for (int kk = 0; kk < 64; kk++) {
            float p[4];
#pragma unroll
            for (int i = 0; i < 4; i++) p[i] = Ss[(ty * 4 + i) * S_S + kk];
            float4 v0 = *(float4*)&Vs[kk * V_S + tx * 8];
            float4 v1 = *(float4*)&Vs[kk * V_S + tx * 8 + 4];
            float va[8] = {v0.x, v0.y, v0.z, v0.w, v1.x, v1.y, v1.z, v1.w};
#pragma unroll
            for (int i = 0; i < 4; i++)
#pragma unroll
                for (int j = 0; j < 8; j++)
                    y[i][j] = fmaf(p[i], va[j], y[i][j]);
        }
    }

    // epilogue: divide by l, octet-permute ([y0,y4,y1,y5,y2,y6,y3,y7]), tf32-round
#pragma unroll
    for (int i = 0; i < 4; i++) {
        int r = ty * 4 + i;
        float invl = 1.f / lS[r];
        float* dst = g_y + ((size_t)(b * SEQ + q0 + r)) * DIMC + h * HD + tx * 8;
        *(float4*)(dst)     = make_float4(tf32r(y[i][0] * invl), tf32r(y[i][4] * invl),
                                          tf32r(y[i][1] * invl), tf32r(y[i][5] * invl));
        *(float4*)(dst + 4) = make_float4(tf32r(y[i][2] * invl), tf32r(y[i][6] * invl),
                                          tf32r(y[i][3] * invl), tf32r(y[i][7] * invl));
    }
}

// ---------------------------------------------------------------------------
extern "C" void kernel_launch(void* const* d_in, const int* in_sizes, int n_in,
                              void* d_out, int out_size) {
    const float* x    = (const float*)d_in[0];
    const float* Wqkv = (const float*)d_in[1];
    const float* Wout = (const float*)d_in[2];
    float*       out  = (float*)d_out;

    float *qkv_p, *y_p, *xr_p, *wq_p, *wo_p;
    cudaGetSymbolAddress((void**)&qkv_p, g_qkv);
    cudaGetSymbolAddress((void**)&y_p,   g_y);
    cudaGetSymbolAddress((void**)&xr_p,  g_xr);
    cudaGetSymbolAddress((void**)&wq_p,  g_wqkv_t);
    cudaGetSymbolAddress((void**)&wo_p,  g_wout_t);

    cudaFuncSetAttribute(gemm_mma, cudaFuncAttributeMaxDynamicSharedMemorySize, GEMM_SMEM);
    cudaFuncSetAttribute(attn_kernel, cudaFuncAttributeMaxDynamicSharedMemorySize,
                         ATTN_SMEM_FLOATS * sizeof(float));

    // prep: permute+round x; transpose+permute+round weights
    permute_cvt_x<<<(TOKENS * DIMC) / (256 * 8), 256>>>(x);
    transpose_permute_cvt<<<dim3(QKVCOLS / 32, KDIM / 32), dim3(32, 8)>>>(Wqkv, wq_p, QKVCOLS);
    transpose_permute_cvt<<<dim3(DIMC / 32, KDIM / 32), dim3(32, 8)>>>(Wout, wo_p, DIMC);

    // 1) QKV projection (tf32 mma.sync)
    gemm_mma<<<dim3(QKVCOLS / GBN, TOKENS / GBM), 256, GEMM_SMEM>>>(xr_p, wq_p, qkv_p, QKVCOLS);

    // 2) RoPE
    rope_kernel<<<(BATCH * SEQ * 2 * NH) / 256, 256>>>();

    // 3) attention (writes permuted+rounded y)
    attn_kernel<<<dim3(SEQ / 64, NH, BATCH), 256, ATTN_SMEM_FLOATS * sizeof(float)>>>();

    // 4) output projection (tf32 mma.sync)
    gemm_mma<<<dim3(DIMC / GBN, TOKENS / GBM), 256, GEMM_SMEM>>>(y_p, wo_p, out, DIMC);
}

// round 9
// speedup vs baseline: 2.6010x; 1.1780x over previous
#include <cuda_runtime.h>
#include <math.h>
#include <stdint.h>

#define BATCH   16
#define SEQ     512
#define DIMC    2048
#define NH      16
#define HD      128
#define TOKENS  (BATCH*SEQ)          /* 8192 */
#define QKVCOLS (3*DIMC)             /* 6144 */
#define KDIM    2048

// ---------------- scratch (__device__ globals, allocation-free rule) --------
__device__ __align__(1024) float g_qkv   [(size_t)TOKENS * QKVCOLS];  // 201MB
__device__ __align__(1024) float g_y     [(size_t)TOKENS * DIMC];     // 67MB (octet-permuted, tf32)
__device__ __align__(1024) float g_xr    [(size_t)TOKENS * DIMC];     // 67MB (octet-permuted, tf32)
__device__ __align__(1024) float g_wqkv_t[(size_t)QKVCOLS * KDIM];    // 50MB [N][K] perm, tf32
__device__ __align__(1024) float g_wout_t[(size_t)DIMC    * KDIM];    // 16MB [N][K] perm, tf32

// ---------------- helpers ---------------------------------------------------
__device__ __forceinline__ uint32_t smem_u32(const void* p) {
    uint32_t a;
    asm("{ .reg .u64 t; cvta.to.shared.u64 t, %1; cvt.u32.u64 %0, t; }" : "=r"(a) : "l"(p));
    return a;
}
__device__ __forceinline__ float tf32r(float x) {
    uint32_t u;
    asm("cvt.rna.tf32.f32 %0, %1;" : "=r"(u) : "f"(x));
    return __uint_as_float(u);
}
#define CP_ASYNC16(dst, src) \
    asm volatile("cp.async.cg.shared.global [%0], [%1], 16;" :: "r"(dst), "l"(src))
#define CP_COMMIT()  asm volatile("cp.async.commit_group;" ::: "memory")
#define CP_WAIT(n)   asm volatile("cp.async.wait_group %0;" :: "n"(n) : "memory")

// m16n8k8 tf32 mma, fp32 accumulate (baseline PTX, works on compute_103)
__device__ __forceinline__ void mma16n8k8(float* d, const uint32_t* a, const uint32_t* b) {
    asm volatile("mma.sync.aligned.m16n8k8.row.col.f32.tf32.tf32.f32 "
                 "{%0,%1,%2,%3}, {%4,%5,%6,%7}, {%8,%9}, {%0,%1,%2,%3};"
                 : "+f"(d[0]), "+f"(d[1]), "+f"(d[2]), "+f"(d[3])
                 : "r"(a[0]), "r"(a[1]), "r"(a[2]), "r"(a[3]),
                   "r"(b[0]), "r"(b[1]));
}

// ---------------------------------------------------------------------------
// tf32 mma.sync GEMM (validated R8): C[M,N] = A[M,K] @ Bt[N,K]^T, K=2048.
// Octet-permuted K layout: [k0,k4,k1,k5,k2,k6,k3,k7] per 8-group.
// ---------------------------------------------------------------------------
#define GBM   128
#define GBN   256
#define GBK   32
#define GNST  3
#define A_ROWSTRIDE 40
#define A_ST  (GBM * A_ROWSTRIDE * 4)
#define B_ST  (GBN * A_ROWSTRIDE * 4)
#define GEMM_SMEM (GNST * (A_ST + B_ST))
#define NCHUNK (KDIM / GBK)

__device__ __forceinline__ void g_load_stage(const float* __restrict__ A,
                                             const float* __restrict__ Bt,
                                             uint32_t smem0, int s, int kc,
                                             int tid, int row0, int col0) {
    const int k0 = kc * GBK;
    const uint32_t a_base = smem0 + s * A_ST;
    const uint32_t b_base = smem0 + GNST * A_ST + s * B_ST;
#pragma unroll
    for (int i = 0; i < 4; i++) {
        int idx = tid + i * 256;
        int r = idx >> 3, seg = idx & 7;
        CP_ASYNC16(a_base + (uint32_t)(r * A_ROWSTRIDE + seg * 4) * 4,
                   A + (size_t)(row0 + r) * KDIM + k0 + seg * 4);
    }
#pragma unroll
    for (int i = 0; i < 8; i++) {
        int idx = tid + i * 256;
        int r = idx >> 3, seg = idx & 7;
        CP_ASYNC16(b_base + (uint32_t)(r * A_ROWSTRIDE + seg * 4) * 4,
                   Bt + (size_t)(col0 + r) * KDIM + k0 + seg * 4);
    }
    CP_COMMIT();
}

__global__ __launch_bounds__(256, 1) void gemm_mma(const float* __restrict__ A,
                                                   const float* __restrict__ Bt,
                                                   float*       __restrict__ C,
                                                   int N) {
    extern __shared__ char sm_raw[];
    const uint32_t smem0 = smem_u32(sm_raw);
    const int tid  = threadIdx.x;
    const int lane = tid & 31, wid = tid >> 5;
    const int wm = wid & 1, wn = wid >> 1;
    const int q  = lane & 3, gr = lane >> 2;
    const int row0 = blockIdx.y * GBM;
    const int col0 = blockIdx.x * GBN;

    float acc[4][8][4];
#pragma unroll
    for (int mi = 0; mi < 4; mi++)
#pragma unroll
        for (int ni = 0; ni < 8; ni++)
#pragma unroll
            for (int v = 0; v < 4; v++) acc[mi][ni][v] = 0.f;

    g_load_stage(A, Bt, smem0, 0, 0, tid, row0, col0);
    g_load_stage(A, Bt, smem0, 1, 1, tid, row0, col0);

    for (int c = 0; c < NCHUNK; c++) {
        const int s = c % GNST;
        if (c + 2 < NCHUNK) {
            CP_WAIT(1);
            __syncthreads();
            g_load_stage(A, Bt, smem0, (c + 2) % GNST, c + 2, tid, row0, col0);
        } else {
            CP_WAIT(0);
            __syncthreads();
        }

        const float2* As = (const float2*)(sm_raw + s * A_ST);
        const float2* Bs = (const float2*)(sm_raw + GNST * A_ST + s * B_ST);

#pragma unroll
        for (int kg = 0; kg < 4; kg++) {
            uint32_t af[4][4], bf[8][2];
#pragma unroll
            for (int mi = 0; mi < 4; mi++) {
                int rowm = wm * 64 + mi * 16 + gr;
                float2 lo = As[rowm * 20 + kg * 4 + q];
                float2 hi = As[(rowm + 8) * 20 + kg * 4 + q];
                af[mi][0] = __float_as_uint(lo.x);
                af[mi][1] = __float_as_uint(hi.x);
                af[mi][2] = __float_as_uint(lo.y);
                af[mi][3] = __float_as_uint(hi.y);
            }
#pragma unroll
            for (int ni = 0; ni < 8; ni++) {
                int rown = wn * 64 + ni * 8 + gr;
                float2 bv = Bs[rown * 20 + kg * 4 + q];
                bf[ni][0] = __float_as_uint(bv.x);
                bf[ni][1] = __float_as_uint(bv.y);
            }
#pragma unroll
            for (int mi = 0; mi < 4; mi++)
#pragma unroll
                for (int ni = 0; ni < 8; ni++)
                    mma16n8k8(acc[mi][ni], af[mi], bf[ni]);
        }
    }

#pragma unroll
    for (int mi = 0; mi < 4; mi++) {
        int rowm = row0 + wm * 64 + mi * 16 + gr;
#pragma unroll
        for (int ni = 0; ni < 8; ni++) {
            int col = col0 + wn * 64 + ni * 8 + 2 * q;
            *(float2*)(C + (size_t)rowm * N + col) =
                make_float2(acc[mi][ni][0], acc[mi][ni][1]);
            *(float2*)(C + (size_t)(rowm + 8) * N + col) =
                make_float2(acc[mi][ni][2], acc[mi][ni][3]);
        }
    }
}

// ---------------------------------------------------------------------------
// prep kernels (validated)
// ---------------------------------------------------------------------------
__global__ void permute_cvt_x(const float* __restrict__ x) {
    size_t o = ((size_t)blockIdx.x * 256 + threadIdx.x) * 8;
    float4 v0 = *(const float4*)(x + o);
    float4 v1 = *(const float4*)(x + o + 4);
    float4 o0 = make_float4(tf32r(v0.x), tf32r(v1.x), tf32r(v0.y), tf32r(v1.y));
    float4 o1 = make_float4(tf32r(v0.z), tf32r(v1.z), tf32r(v0.w), tf32r(v1.w));
    *(float4*)(g_xr + o)     = o0;
    *(float4*)(g_xr + o + 4) = o1;
}

__global__ void transpose_permute_cvt(const float* __restrict__ W,
                                      float* __restrict__ Wt, int N) {
    __shared__ float t[32][33];
    int k0 = blockIdx.y * 32, n0 = blockIdx.x * 32;
    int tx = threadIdx.x, ty = threadIdx.y;
#pragma unroll
    for (int i = 0; i < 32; i += 8)
        t[ty + i][tx] = W[(size_t)(k0 + ty + i) * N + n0 + tx];
    __syncthreads();
    int g = tx >> 3, p = tx & 7;
    int lk = g * 8 + (p >> 1) + ((p & 1) << 2);
#pragma unroll
    for (int i = 0; i < 32; i += 8)
        Wt[(size_t)(n0 + ty + i) * KDIM + k0 + tx] = tf32r(t[lk][ty + i]);
}

// ---------------------------------------------------------------------------
// RoPE (validated)
// ---------------------------------------------------------------------------
__global__ void rope_kernel() {
    int idx = blockIdx.x * blockDim.x + threadIdx.x;
    int h = idx & 15;
    int s = (idx >> 4) & 1;
    int t = (idx >> 5) & 511;
    int b = idx >> 14;
    size_t base = ((size_t)(b * SEQ + t)) * QKVCOLS + (size_t)s * DIMC + h * HD;
#pragma unroll
    for (int i = 0; i < 8; i++) {
        float inv  = (float)pow(10000.0, -(double)i / 8.0);
        float freq = (float)t * inv;
        float c  = (float)cos((double)freq);
        float sn = (float)sin((double)freq);
        float x1 = g_qkv[base + i];
        float x2 = g_qkv[base + 8 + i];
        g_qkv[base + i]     = x1 * c - x2 * sn;
        g_qkv[base + 8 + i] = x2 * c + x1 * sn;
    }
}

// ---------------------------------------------------------------------------
// Tensor-core flash attention.
// CTA = 256 thr, tile = 64 q-rows x full head. QK^T: 2-term tf32 split
// (hi*hi + hi*lo + lo*hi). PV: single tf32. Softmax: __expf, 4 thr/row.
// All smem operands octet-permuted along the MMA k-dim for float2 frags.
// Output written octet-permuted + tf32 (feeds gemm_mma directly).
// ---------------------------------------------------------------------------
#define QS_S 132                 /* floats per Q/K row (128 + 4 pad) */
#define VT_S 72                  /* floats per Vt row (64 + 8 pad)   */
#define PS_S 72
#define AQHI 0
#define AQLO (64*QS_S)
#define AKHI (2*64*QS_S)
#define AKLO (3*64*QS_S)
#define AVT  (4*64*QS_S)         /* 33792 */
#define APS  (AVT + 128*VT_S)    /* 43008 */
#define AMS  (APS + 64*PS_S)     /* 47616 */
#define ALS  (AMS + 64)
#define AAS  (ALS + 64)
#define ATTN_SMEM ((AAS + 64) * 4)   /* 191232 B */

__global__ __launch_bounds__(256, 1) void attn_tc_kernel() {
    extern __shared__ float sm[];
    const int tid  = threadIdx.x;
    const int lane = tid & 31, wid = tid >> 5;
    const int wm = wid & 3, wn = wid >> 2;      // warp grid 4(m) x 2(n)
    const int gr = lane >> 2, q = lane & 3;
    const int qt = blockIdx.x;
    const int h  = blockIdx.y;
    const int b  = blockIdx.z;
    const int q0 = qt * 64;
    const float scale = 0.08838834764831845f;

    // ---- load Q once: split into tf32 hi/lo, octet-permuted along d ----
    for (int i4 = tid; i4 < 64 * 32; i4 += 256) {
        int r = i4 >> 5;                 // warp-uniform row
        int d = (i4 & 31) << 2;          // 0,4,...,124
        float4 v = *(const float4*)(g_qkv +
                    ((size_t)(b * SEQ + q0 + r)) * QKVCOLS + h * HD + d);
        int pb = (d & ~7) + ((d >> 2) & 1);     // phys base; stores at pb+2j
        float vals[4] = {v.x * scale, v.y * scale, v.z * scale, v.w * scale};
#pragma unroll
        for (int j = 0; j < 4; j++) {
            float hi = tf32r(vals[j]);
            float lo = tf32r(vals[j] - hi);
            sm[AQHI + r * QS_S + pb + 2 * j] = hi;
            sm[AQLO + r * QS_S + pb + 2 * j] = lo;
        }
    }
    if (tid < 64) { sm[AMS + tid] = -INFINITY; sm[ALS + tid] = 0.f; }

    float y[8][4];
#pragma unroll
    for (int ni = 0; ni < 8; ni++)
#pragma unroll
        for (int v = 0; v < 4; v++) y[ni][v] = 0.f;

    for (int kt = 0; kt <= qt; kt++) {
        const int k0 = kt * 64;
        __syncthreads();   // prev PV done with Ps/Vt; Q + stats ready (iter 0)

        // ---- K tile: tf32 hi/lo split, octet-permuted along d ----
        for (int i4 = tid; i4 < 64 * 32; i4 += 256) {
            int r = i4 >> 5;
            int d = (i4 & 31) << 2;
            float4 v = *(const float4*)(g_qkv +
                        ((size_t)(b * SEQ + k0 + r)) * QKVCOLS + DIMC + h * HD + d);
            int pb = (d & ~7) + ((d >> 2) & 1);
            float vals[4] = {v.x, v.y, v.z, v.w};
#pragma unroll
            for (int j = 0; j < 4; j++) {
                float hi = tf32r(vals[j]);
                float lo = tf32r(vals[j] - hi);
                sm[AKHI + r * QS_S + pb + 2 * j] = hi;
                sm[AKLO + r * QS_S + pb + 2 * j] = lo;
            }
        }
        // ---- V tile: transposed Vt[d][perm(r)], tf32. row-per-lane => conflict-free
        for (int i4 = tid; i4 < 64 * 32; i4 += 256) {
            int r  = i4 & 63;            // lane-varying row
            int dg = i4 >> 6;            // 0..31
            float4 v = *(const float4*)(g_qkv +
                        ((size_t)(b * SEQ + k0 + r)) * QKVCOLS + 2 * DIMC + h * HD + 4 * dg);
            int ro = r & 7;
            int pr = (r & ~7) + 2 * (ro & 3) + (ro >> 2);
            sm[AVT + (4 * dg + 0) * VT_S + pr] = tf32r(v.x);
            sm[AVT + (4 * dg + 1) * VT_S + pr] = tf32r(v.y);
            sm[AVT + (4 * dg + 2) * VT_S + pr] = tf32r(v.z);
            sm[AVT + (4 * dg + 3) * VT_S + pr] = tf32r(v.w);
        }
        __syncthreads();

        // ---- S = Q K^T, split tf32 (hi*hi + hi*lo + lo*hi) ----
        float s_acc[4][4];
#pragma unroll
        for (int ni = 0; ni < 4; ni++)
#pragma unroll
            for (int v = 0; v < 4; v++) s_acc[ni][v] = 0.f;

        const int rowm = wm * 16 + gr;
        const float2* Qh2 = (const float2*)(sm + AQHI);
        const float2* Ql2 = (const float2*)(sm + AQLO);
        const float2* Kh2 = (const float2*)(sm + AKHI);
        const float2* Kl2 = (const float2*)(sm + AKLO);

#pragma unroll
        for (int kg = 0; kg < 16; kg++) {
            uint32_t ah[4], al[4];
            {
                float2 h0 = Qh2[rowm * 66 + kg * 4 + q];
                float2 h1 = Qh2[(rowm + 8) * 66 + kg * 4 + q];
                float2 l0 = Ql2[rowm * 66 + kg * 4 + q];
                float2 l1 = Ql2[(rowm + 8) * 66 + kg * 4 + q];
                ah[0] = __float_as_uint(h0.x); ah[1] = __float_as_uint(h1.x);
                ah[2] = __float_as_uint(h0.y); ah[3] = __float_as_uint(h1.y);
                al[0] = __float_as_uint(l0.x); al[1] = __float_as_uint(l1.x);
                al[2] = __float_as_uint(l0.y); al[3] = __float_as_uint(l1.y);
            }
#pragma unroll
            for (int ni = 0; ni < 4; ni++) {
                int rown = wn * 32 + ni * 8 + gr;
                float2 bh = Kh2[rown * 66 + kg * 4 + q];
                float2 bl = Kl2[rown * 66 + kg * 4 + q];
                uint32_t bhf[2] = {__float_as_uint(bh.x), __float_as_uint(bh.y)};
                uint32_t blf[2] = {__float_as_uint(bl.x), __float_as_uint(bl.y)};
                mma16n8k8(s_acc[ni], ah, bhf);
                mma16n8k8(s_acc[ni], ah, blf);
                mma16n8k8(s_acc[ni], al, bhf);
            }
        }

        // store S into Ps, octet-permuted cols
        {
            int p0 = (q < 2) ? 4 * q : 4 * q - 7;
#pragma unroll
            for (int ni = 0; ni < 4; ni++) {
                int colb = wn * 32 + ni * 8;
                sm[APS + rowm * PS_S + colb + p0]           = s_acc[ni][0];
                sm[APS + rowm * PS_S + colb + p0 + 2]       = s_acc[ni][1];
                sm[APS + (rowm + 8) * PS_S + colb + p0]     = s_acc[ni][2];
                sm[APS + (rowm + 8) * PS_S + colb + p0 + 2] = s_acc[ni][3];
            }
        }
        __syncthreads();

        // ---- online softmax: 4 threads per row ----
        {
            int r = tid >> 2, seg = tid & 3;
            float* prow = sm + APS + r * PS_S + seg * 16;
            const bool diag = (kt == qt);
            float vals[16];
            float mx = -INFINITY;
#pragma unroll
            for (int j = 0; j < 16; j++) {
                int p = seg * 16 + j;
                float s = prow[j];
                if (diag) {
                    int lc = (p & ~7) + ((p & 7) >> 1) + ((p & 1) << 2);
                    if (lc > r) s = -INFINITY;
                }
                vals[j] = s;
                mx = fmaxf(mx, s);
            }
            mx = fmaxf(mx, __shfl_xor_sync(0xffffffffu, mx, 1));
            mx = fmaxf(mx, __shfl_xor_sync(0xffffffffu, mx, 2));
            float mold = sm[AMS + r];
            float mnew = fmaxf(mold, mx);
            float sum = 0.f;
#pragma unroll
            for (int j = 0; j < 16; j++) {
                float p = (vals[j] == -INFINITY) ? 0.f : tf32r(__expf(vals[j] - mnew));
                prow[j] = p;
                sum += p;
            }
            sum += __shfl_xor_sync(0xffffffffu, sum, 1);
            sum += __shfl_xor_sync(0xffffffffu, sum, 2);
            if (seg == 0) {
                float alpha = __expf(mold - mnew);
                sm[ALS + r] = sm[ALS + r] * alpha + sum;
                sm[AMS + r] = mnew;
                sm[AAS + r] = alpha;
            }
        }
        __syncthreads();

        // ---- Y = Y*alpha + P @ V (tf32) ----
        {
            float a0 = sm[AAS + rowm];
            float a1 = sm[AAS + rowm + 8];
#pragma unroll
            for (int ni = 0; ni < 8; ni++) {
                y[ni][0] *= a0; y[ni][1] *= a0;
                y[ni][2] *= a1; y[ni][3] *= a1;
            }
            const float2* Ps2 = (const float2*)(sm + APS);
            const float2* Vt2 = (const float2*)(sm + AVT);
#pragma unroll
            for (int kg = 0; kg < 8; kg++) {
                float2 p0 = Ps2[rowm * 36 + kg * 4 + q];
                float2 p1 = Ps2[(rowm + 8) * 36 + kg * 4 + q];
                uint32_t ua[4] = {__float_as_uint(p0.x), __float_as_uint(p1.x),
                                  __float_as_uint(p0.y), __float_as_uint(p1.y)};
#pragma unroll
                for (int ni = 0; ni < 8; ni++) {
                    int rown = wn * 64 + ni * 8 + gr;
                    float2 bv = Vt2[rown * 36 + kg * 4 + q];
                    uint32_t ub[2] = {__float_as_uint(bv.x), __float_as_uint(bv.y)};
                    mma16n8k8(y[ni], ua, ub);
                }
            }
        }
    }

    // ---- epilogue: /l, octet-permute d, tf32, write g_y ----
    {
        const int rowm = wm * 16 + gr;
        float invl0 = 1.f / sm[ALS + rowm];
        float invl1 = 1.f / sm[ALS + rowm + 8];
        int p0 = (q < 2) ? 4 * q : 4 * q - 7;
        size_t t0 = ((size_t)(b * SEQ + q0 + rowm)) * DIMC + h * HD;
        size_t t1 = t0 + 8 * DIMC;
#pragma unroll
        for (int ni = 0; ni < 8; ni++) {
            int colb = wn * 64 + ni * 8;
            g_y[t0 + colb + p0]     = tf32r(y[ni][0] * invl0);
            g_y[t0 + colb + p0 + 2] = tf32r(y[ni][1] * invl0);
            g_y[t1 + colb + p0]     = tf32r(y[ni][2] * invl1);
            g_y[t1 + colb + p0 + 2] = tf32r(y[ni][3] * invl1);
        }
    }
}

// ---------------------------------------------------------------------------
extern "C" void kernel_launch(void* const* d_in, const int* in_sizes, int n_in,
                              void* d_out, int out_size) {
    const float* x    = (const float*)d_in[0];
    const float* Wqkv = (const float*)d_in[1];
    const float* Wout = (const float*)d_in[2];
    float*       out  = (float*)d_out;

    float *qkv_p, *y_p, *xr_p, *wq_p, *wo_p;
    cudaGetSymbolAddress((void**)&qkv_p, g_qkv);
    cudaGetSymbolAddress((void**)&y_p,   g_y);
    cudaGetSymbolAddress((void**)&xr_p,  g_xr);
    cudaGetSymbolAddress((void**)&wq_p,  g_wqkv_t);
    cudaGetSymbolAddress((void**)&wo_p,  g_wout_t);

    cudaFuncSetAttribute(gemm_mma, cudaFuncAttributeMaxDynamicSharedMemorySize, GEMM_SMEM);
    cudaFuncSetAttribute(attn_tc_kernel, cudaFuncAttributeMaxDynamicSharedMemorySize,
                         ATTN_SMEM);

    // prep
    permute_cvt_x<<<(TOKENS * DIMC) / (256 * 8), 256>>>(x);
    transpose_permute_cvt<<<dim3(QKVCOLS / 32, KDIM / 32), dim3(32, 8)>>>(Wqkv, wq_p, QKVCOLS);
    transpose_permute_cvt<<<dim3(DIMC / 32, KDIM / 32), dim3(32, 8)>>>(Wout, wo_p, DIMC);

    // 1) QKV projection
    gemm_mma<<<dim3(QKVCOLS / GBN, TOKENS / GBM), 256, GEMM_SMEM>>>(xr_p, wq_p, qkv_p, QKVCOLS);

    // 2) RoPE
    rope_kernel<<<(BATCH * SEQ * 2 * NH) / 256, 256>>>();

    // 3) attention (tensor cores)
    attn_tc_kernel<<<dim3(SEQ / 64, NH, BATCH), 256, ATTN_SMEM>>>();

    // 4) output projection
    gemm_mma<<<dim3(DIMC / GBN, TOKENS / GBM), 256, GEMM_SMEM>>>(y_p, wo_p, out, DIMC);
}